// round 10
// baseline (speedup 1.0000x reference)
#include <cuda_runtime.h>
#include <cuda_fp16.h>
#include <cstdint>

// Conv (32,64,64,128) NHWC fp32 * w(256,1152) + b -> (32,62,62,256) fp32
// via Winograd F(2x2,3x3):  y = A^T [ (G g G^T) .* (B^T d B) ] A
// 16 element-wise GEMMs:  M_pos[m',f] = sum_c At_pos[m',c] * Wt_pos[f,c]
// MACs: 16 * 30848 * 256 * 128 = 16.2G  (2.25x fewer than direct conv)

#define NIMG 32
#define HI 64
#define WI 64
#define CI 128
#define FO 256
#define HOUT 62
#define NT 31          // winograd tiles per spatial dim
#define MW 30752       // 32*31*31
#define MPAD 30848     // 241*128
#define NPOS 16

__device__ __align__(16) __half g_wT[(size_t)NPOS * FO * CI];     // [pos][f][c]
__device__ __align__(16) __half g_inT[(size_t)NPOS * MPAD * CI];  // [pos][m'][c]
__device__ __align__(16) __half g_M[(size_t)NPOS * MPAD * FO];    // [pos][m'][f]

// ---------------- common helpers ----------------
__device__ __forceinline__ uint32_t smem_u32(const void* p) {
    uint32_t a;
    asm("{ .reg .u64 t; cvta.to.shared.u64 t, %1; cvt.u32.u64 %0, t; }"
        : "=r"(a) : "l"(p));
    return a;
}
__device__ __forceinline__ void cpa16(uint32_t dst, const void* src) {
    asm volatile("cp.async.cg.shared.global [%0], [%1], 16;"
                 :: "r"(dst), "l"(src));
}
#define CP_COMMIT() asm volatile("cp.async.commit_group;" ::: "memory")
#define CP_WAIT1()  asm volatile("cp.async.wait_group 1;" ::: "memory")
#define CP_WAIT0()  asm volatile("cp.async.wait_group 0;" ::: "memory")

__device__ __forceinline__ void ldm4(uint32_t* r, uint32_t a) {
    asm volatile("ldmatrix.sync.aligned.m8n8.x4.shared.b16 {%0,%1,%2,%3}, [%4];"
                 : "=r"(r[0]), "=r"(r[1]), "=r"(r[2]), "=r"(r[3]) : "r"(a));
}
__device__ __forceinline__ void mma16816(float* c, const uint32_t* a,
                                         uint32_t b0, uint32_t b1) {
    asm volatile(
        "mma.sync.aligned.m16n8k16.row.col.f32.f16.f16.f32 "
        "{%0,%1,%2,%3}, {%4,%5,%6,%7}, {%8,%9}, {%0,%1,%2,%3};"
        : "+f"(c[0]), "+f"(c[1]), "+f"(c[2]), "+f"(c[3])
        : "r"(a[0]), "r"(a[1]), "r"(a[2]), "r"(a[3]), "r"(b0), "r"(b1));
}

__device__ __forceinline__ float4 f4add(float4 a, float4 b) {
    return make_float4(a.x + b.x, a.y + b.y, a.z + b.z, a.w + b.w);
}
__device__ __forceinline__ float4 f4sub(float4 a, float4 b) {
    return make_float4(a.x - b.x, a.y - b.y, a.z - b.z, a.w - b.w);
}
__device__ __forceinline__ uint2 pack4h(float4 v) {
    __half2 p0 = __floats2half2_rn(v.x, v.y);
    __half2 p1 = __floats2half2_rn(v.z, v.w);
    uint2 r;
    r.x = *reinterpret_cast<uint32_t*>(&p0);
    r.y = *reinterpret_cast<uint32_t*>(&p1);
    return r;
}

// ---------------- K1: input + weight transforms ----------------
#define K1_IN_BLOCKS 3844          // 30752 m' * 32 cgroups / 256
#define K1_W_BLOCKS  128           // 256 f * 128 c / 256

__global__ __launch_bounds__(256)
void winograd_transform(const float* __restrict__ in, const float* __restrict__ w) {
    const int b = blockIdx.x;
    if (b < K1_IN_BLOCKS) {
        // ---- input transform: A~ = B^T d B per (m', 4 channels) ----
        const int gt = b * 256 + threadIdx.x;
        const int mp = gt >> 5;            // m' index
        const int c0 = (gt & 31) * 4;
        const int n  = mp / (NT * NT);
        const int r  = mp - n * (NT * NT);
        const int th = r / NT;
        const int tw = r - th * NT;
        const float* base = in + (((long)(n * HI + 2 * th)) * WI + 2 * tw) * CI + c0;

        float4 t[4][4];
#pragma unroll
        for (int q = 0; q < 4; q++) {
            float4 d0 = *reinterpret_cast<const float4*>(base + (0 * WI + q) * CI);
            float4 d1 = *reinterpret_cast<const float4*>(base + (1 * WI + q) * CI);
            float4 d2 = *reinterpret_cast<const float4*>(base + (2 * WI + q) * CI);
            float4 d3 = *reinterpret_cast<const float4*>(base + (3 * WI + q) * CI);
            t[0][q] = f4sub(d0, d2);
            t[1][q] = f4add(d1, d2);
            t[2][q] = f4sub(d2, d1);
            t[3][q] = f4sub(d1, d3);
        }
        __half* dst0 = g_inT + (long)mp * CI + c0;
#pragma unroll
        for (int i = 0; i < 4; i++) {
            float4 a0 = f4sub(t[i][0], t[i][2]);
            float4 a1 = f4add(t[i][1], t[i][2]);
            float4 a2 = f4sub(t[i][2], t[i][1]);
            float4 a3 = f4sub(t[i][1], t[i][3]);
            const long ps = (long)MPAD * CI;
            *reinterpret_cast<uint2*>(dst0 + (long)(4 * i + 0) * ps) = pack4h(a0);
            *reinterpret_cast<uint2*>(dst0 + (long)(4 * i + 1) * ps) = pack4h(a1);
            *reinterpret_cast<uint2*>(dst0 + (long)(4 * i + 2) * ps) = pack4h(a2);
            *reinterpret_cast<uint2*>(dst0 + (long)(4 * i + 3) * ps) = pack4h(a3);
        }
    } else {
        // ---- weight transform: W~ = G g G^T per (f, c) ----
        const int wt = (b - K1_IN_BLOCKS) * 256 + threadIdx.x;   // < 32768
        const int f = wt >> 7;
        const int c = wt & 127;
        float g[3][3];
#pragma unroll
        for (int i = 0; i < 3; i++)
#pragma unroll
            for (int j = 0; j < 3; j++)
                g[i][j] = w[(long)f * 1152 + (i * 3 + j) * CI + c];
        float u[4][3];
#pragma unroll
        for (int k = 0; k < 3; k++) {
            u[0][k] = g[0][k];
            u[1][k] = 0.5f * (g[0][k] + g[1][k] + g[2][k]);
            u[2][k] = 0.5f * (g[0][k] - g[1][k] + g[2][k]);
            u[3][k] = g[2][k];
        }
        __half* dst = g_wT + (long)f * CI + c;
#pragma unroll
        for (int i = 0; i < 4; i++) {
            float v0 = u[i][0];
            float v1 = 0.5f * (u[i][0] + u[i][1] + u[i][2]);
            float v2 = 0.5f * (u[i][0] - u[i][1] + u[i][2]);
            float v3 = u[i][2];
            const long ps = (long)FO * CI;
            dst[(long)(4 * i + 0) * ps] = __float2half(v0);
            dst[(long)(4 * i + 1) * ps] = __float2half(v1);
            dst[(long)(4 * i + 2) * ps] = __float2half(v2);
            dst[(long)(4 * i + 3) * ps] = __float2half(v3);
        }
    }
}

// ---------------- K2: batched GEMM over pos (4 pos per CTA) ----------------
// Tile 128m' x 128f, 8 warps (2Mx4N), warp tile 64x32 (R5-validated).
// K = 128 per pos -> 2 chunks of 64; 4 pos -> 8 flat chunks, 3-stage pipeline.
#define GSTAGE 32768               // A 16KB + B 16KB
#define GSMEM (3 * GSTAGE)         // 96KB -> 2 CTAs/SM

__device__ __forceinline__ void wg_prefetch(uint32_t sb, int stage, int fc, int pos0,
                                            int m_base, int n_base, int tid) {
    const int pos   = pos0 + (fc >> 1);
    const int khalf = (fc & 1) * 64;
    const uint32_t st = sb + stage * GSTAGE;
    const int row = tid >> 1;
    const int h   = tid & 1;
    const __half* asrc = g_inT + ((long)pos * MPAD + m_base + row) * CI + khalf;
    const __half* bsrc = g_wT  + ((long)pos * FO   + n_base + row) * CI + khalf;
#pragma unroll
    for (int j = 0; j < 4; j++) {
        const int c  = h * 4 + j;
        const int cs = c ^ (row & 7);
        cpa16(st +         row * 128 + cs * 16, asrc + c * 8);
        cpa16(st + 16384 + row * 128 + cs * 16, bsrc + c * 8);
    }
}

__global__ __launch_bounds__(256, 2)
void winograd_gemm() {
    extern __shared__ char smem[];
    const uint32_t sb = smem_u32(smem);
    const int tid  = threadIdx.x;
    const int lane = tid & 31;
    const int wid  = tid >> 5;
    const int warpM = wid >> 2;          // 0..1 -> 64-row slab
    const int warpN = wid & 3;           // 0..3 -> 32-col slab
    const int m_base = blockIdx.x * 128; // 241 tiles over MPAD
    const int n_base = blockIdx.y * 128; // 2 tiles
    const int pos0   = blockIdx.z * 4;   // 4 pos-quads

    float acc[4][4][4];
#pragma unroll
    for (int i = 0; i < 4; i++)
#pragma unroll
        for (int j = 0; j < 4; j++)
#pragma unroll
            for (int k = 0; k < 4; k++) acc[i][j][k] = 0.0f;

    wg_prefetch(sb, 0, 0, pos0, m_base, n_base, tid); CP_COMMIT();
    wg_prefetch(sb, 1, 1, pos0, m_base, n_base, tid); CP_COMMIT();

#pragma unroll
    for (int fc = 0; fc < 8; fc++) {
        CP_WAIT1();
        __syncthreads();
        if (fc < 6) wg_prefetch(sb, (fc + 2) % 3, fc + 2, pos0, m_base, n_base, tid);
        CP_COMMIT();

        const uint32_t st = sb + (fc % 3) * GSTAGE;
#pragma unroll
        for (int s = 0; s < 4; s++) {
            uint32_t ah[4][4], bh[2][4];
#pragma unroll
            for (int mb = 0; mb < 4; mb++) {
                const int row = warpM * 64 + mb * 16 + (lane & 15);
                const int c   = s * 2 + (lane >> 4);
                const int cs  = c ^ (row & 7);
                ldm4(ah[mb], st + row * 128 + cs * 16);
            }
#pragma unroll
            for (int i = 0; i < 2; i++) {
                const int row = warpN * 32 + i * 16 + (lane & 15);
                const int c   = s * 2 + (lane >> 4);
                const int cs  = c ^ (row & 7);
                ldm4(bh[i], st + 16384 + row * 128 + cs * 16);
            }
#pragma unroll
            for (int mb = 0; mb < 4; mb++)
#pragma unroll
                for (int i = 0; i < 2; i++)
#pragma unroll
                    for (int h = 0; h < 2; h++)
                        mma16816(acc[mb][i * 2 + h], ah[mb],
                                 bh[i][h], bh[i][h + 2]);
        }

        if (fc & 1) {
            // epilogue: write M tile (fp16) for pos = pos0 + (fc>>1)
            const int pos = pos0 + (fc >> 1);
            __half* mbase = g_M + (long)pos * MPAD * FO;
#pragma unroll
            for (int nb = 0; nb < 4; nb++) {
                const int n = n_base + warpN * 32 + nb * 8 + (lane & 3) * 2;
#pragma unroll
                for (int mb = 0; mb < 4; mb++) {
                    const long m0 = (long)m_base + warpM * 64 + mb * 16 + (lane >> 2);
                    const float* c = acc[mb][nb];
                    __half2 h0 = __floats2half2_rn(c[0], c[1]);
                    __half2 h1 = __floats2half2_rn(c[2], c[3]);
                    *reinterpret_cast<__half2*>(mbase + m0 * FO + n)       = h0;
                    *reinterpret_cast<__half2*>(mbase + (m0 + 8) * FO + n) = h1;
                }
            }
            if (fc < 7) {
#pragma unroll
                for (int i = 0; i < 4; i++)
#pragma unroll
                    for (int j = 0; j < 4; j++)
#pragma unroll
                        for (int k = 0; k < 4; k++) acc[i][j][k] = 0.0f;
            }
        }
    }
    CP_WAIT0();
}

// ---------------- K3: output transform y = A^T M A + bias ----------------
// Streaming form: y[a][b] = bias + sum_p c_p(a,b) * M_p,
//   c_p(a,b) = AT[a][p>>2] * AT[b][p&3],  AT = [[1,1,1,0],[0,1,-1,-1]]
// Each thread: (m', 8 filters); 16 x 16B independent loads; 4 x 32B stores.
#define K3_BLOCKS (MW * 32 / 256)   // 3844

__global__ __launch_bounds__(256)
void winograd_output(const float* __restrict__ bias, float* __restrict__ out) {
    const int gt = blockIdx.x * 256 + threadIdx.x;
    const int mp = gt >> 5;
    const int f0 = (gt & 31) * 8;

    uint4 mraw[16];
#pragma unroll
    for (int p = 0; p < 16; p++)
        mraw[p] = *reinterpret_cast<const uint4*>(
            g_M + ((long)p * MPAD + mp) * FO + f0);

    float4 bv0 = *reinterpret_cast<const float4*>(bias + f0);
    float4 bv1 = *reinterpret_cast<const float4*>(bias + f0 + 4);

    // y[a][b] as 4 float2 each (8 filters)
    float2 y[2][2][4];
#pragma unroll
    for (int a = 0; a < 2; a++)
#pragma unroll
        for (int b = 0; b < 2; b++) {
            y[a][b][0] = make_float2(bv0.x, bv0.y);
            y[a][b][1] = make_float2(bv0.z, bv0.w);
            y[a][b][2] = make_float2(bv1.x, bv1.y);
            y[a][b][3] = make_float2(bv1.z, bv1.w);
        }

    // coefficient table AT[2][4]
    const float AT0[4] = {1.f, 1.f, 1.f, 0.f};
    const float AT1[4] = {0.f, 1.f, -1.f, -1.f};
#pragma unroll
    for (int p = 0; p < 16; p++) {
        const int i = p >> 2, j = p & 3;
        const float ca0 = AT0[i], ca1 = AT1[i];
        const float cb0 = AT0[j], cb1 = AT1[j];
        const uint32_t* wv = reinterpret_cast<const uint32_t*>(&mraw[p]);
#pragma unroll
        for (int w = 0; w < 4; w++) {
            const __half2 h = *reinterpret_cast<const __half2*>(&wv[w]);
            const float2 m = __half22float2(h);
            const float c00 = ca0 * cb0, c01 = ca0 * cb1;
            const float c10 = ca1 * cb0, c11 = ca1 * cb1;
            if (c00 != 0.f) { y[0][0][w].x += c00 * m.x; y[0][0][w].y += c00 * m.y; }
            if (c01 != 0.f) { y[0][1][w].x += c01 * m.x; y[0][1][w].y += c01 * m.y; }
            if (c10 != 0.f) { y[1][0][w].x += c10 * m.x; y[1][0][w].y += c10 * m.y; }
            if (c11 != 0.f) { y[1][1][w].x += c11 * m.x; y[1][1][w].y += c11 * m.y; }
        }
    }

    const int n  = mp / (NT * NT);
    const int r  = mp - n * (NT * NT);
    const int th = r / NT;
    const int tw = r - th * NT;
#pragma unroll
    for (int a = 0; a < 2; a++)
#pragma unroll
        for (int b = 0; b < 2; b++) {
            float* dst = out + (((long)(n * HOUT + 2 * th + a)) * HOUT
                                + (2 * tw + b)) * FO + f0;
            float4 v0, v1;
            v0.x = y[a][b][0].x; v0.y = y[a][b][0].y;
            v0.z = y[a][b][1].x; v0.w = y[a][b][1].y;
            v1.x = y[a][b][2].x; v1.y = y[a][b][2].y;
            v1.z = y[a][b][3].x; v1.w = y[a][b][3].y;
            *reinterpret_cast<float4*>(dst)     = v0;
            *reinterpret_cast<float4*>(dst + 4) = v1;
        }
}

extern "C" void kernel_launch(void* const* d_in, const int* in_sizes, int n_in,
                              void* d_out, int out_size) {
    const float* in   = (const float*)d_in[0];
    const float* w    = (const float*)d_in[1];
    const float* bias = (const float*)d_in[2];
    float* out        = (float*)d_out;

    winograd_transform<<<K1_IN_BLOCKS + K1_W_BLOCKS, 256>>>(in, w);

    cudaFuncSetAttribute(winograd_gemm,
                         cudaFuncAttributeMaxDynamicSharedMemorySize, GSMEM);
    dim3 grid(MPAD / 128, 2, 4);   // (241, 2, 4)
    winograd_gemm<<<grid, 256, GSMEM>>>();

    winograd_output<<<K3_BLOCKS, 256>>>(bias, out);
}

// round 11
// speedup vs baseline: 1.4241x; 1.4241x over previous
#include <cuda_runtime.h>
#include <cuda_fp16.h>
#include <cstdint>

// Conv (32,64,64,128) NHWC fp32 * w(256,1152) + b -> (32,62,62,256) fp32
// via Winograd F(2x2,3x3):  y = A^T [ (G g G^T) .* (B^T d B) ] A
// 16 element-wise GEMMs:  M_pos[m',f] = sum_c At_pos[m',c] * Wt_pos[f,c]
// MACs: 16 * 30848 * 256 * 128 = 16.2G  (2.25x fewer than direct conv)
// R11 = R9 (validated 253us) + K1 explicit load batching (MLP=16).

#define NIMG 32
#define HI 64
#define WI 64
#define CI 128
#define FO 256
#define HOUT 62
#define NT 31          // winograd tiles per spatial dim
#define MW 30752       // 32*31*31
#define MPAD 30848     // 241*128
#define NPOS 16

__device__ __align__(16) __half g_wT[(size_t)NPOS * FO * CI];     // [pos][f][c]
__device__ __align__(16) __half g_inT[(size_t)NPOS * MPAD * CI];  // [pos][m'][c]
__device__ __align__(16) __half g_M[(size_t)NPOS * MPAD * FO];    // [pos][m'][f]

// ---------------- common helpers ----------------
__device__ __forceinline__ uint32_t smem_u32(const void* p) {
    uint32_t a;
    asm("{ .reg .u64 t; cvta.to.shared.u64 t, %1; cvt.u32.u64 %0, t; }"
        : "=r"(a) : "l"(p));
    return a;
}
__device__ __forceinline__ void cpa16(uint32_t dst, const void* src) {
    asm volatile("cp.async.cg.shared.global [%0], [%1], 16;"
                 :: "r"(dst), "l"(src));
}
#define CP_COMMIT() asm volatile("cp.async.commit_group;" ::: "memory")
#define CP_WAIT1()  asm volatile("cp.async.wait_group 1;" ::: "memory")
#define CP_WAIT0()  asm volatile("cp.async.wait_group 0;" ::: "memory")

__device__ __forceinline__ void ldm4(uint32_t* r, uint32_t a) {
    asm volatile("ldmatrix.sync.aligned.m8n8.x4.shared.b16 {%0,%1,%2,%3}, [%4];"
                 : "=r"(r[0]), "=r"(r[1]), "=r"(r[2]), "=r"(r[3]) : "r"(a));
}
__device__ __forceinline__ void mma16816(float* c, const uint32_t* a,
                                         uint32_t b0, uint32_t b1) {
    asm volatile(
        "mma.sync.aligned.m16n8k16.row.col.f32.f16.f16.f32 "
        "{%0,%1,%2,%3}, {%4,%5,%6,%7}, {%8,%9}, {%0,%1,%2,%3};"
        : "+f"(c[0]), "+f"(c[1]), "+f"(c[2]), "+f"(c[3])
        : "r"(a[0]), "r"(a[1]), "r"(a[2]), "r"(a[3]), "r"(b0), "r"(b1));
}

__device__ __forceinline__ float4 f4add(float4 a, float4 b) {
    return make_float4(a.x + b.x, a.y + b.y, a.z + b.z, a.w + b.w);
}
__device__ __forceinline__ float4 f4sub(float4 a, float4 b) {
    return make_float4(a.x - b.x, a.y - b.y, a.z - b.z, a.w - b.w);
}
__device__ __forceinline__ uint2 pack4h(float4 v) {
    __half2 p0 = __floats2half2_rn(v.x, v.y);
    __half2 p1 = __floats2half2_rn(v.z, v.w);
    uint2 r;
    r.x = *reinterpret_cast<uint32_t*>(&p0);
    r.y = *reinterpret_cast<uint32_t*>(&p1);
    return r;
}

// ---------------- K1: input + weight transforms ----------------
#define K1_IN_BLOCKS 3844          // 30752 m' * 32 cgroups / 256
#define K1_W_BLOCKS  128           // 256 f * 128 c / 256

__global__ __launch_bounds__(256)
void winograd_transform(const float* __restrict__ in, const float* __restrict__ w) {
    const int b = blockIdx.x;
    if (b < K1_IN_BLOCKS) {
        // ---- input transform: A~ = B^T d B per (m', 4 channels) ----
        const int gt = b * 256 + threadIdx.x;
        const int mp = gt >> 5;            // m' index
        const int c0 = (gt & 31) * 4;
        const int n  = mp / (NT * NT);
        const int r  = mp - n * (NT * NT);
        const int th = r / NT;
        const int tw = r - th * NT;
        const float* base = in + (((long)(n * HI + 2 * th)) * WI + 2 * tw) * CI + c0;

        // issue ALL 16 independent loads first (MLP=16)
        float4 d[4][4];
#pragma unroll
        for (int i = 0; i < 4; i++)
#pragma unroll
            for (int q = 0; q < 4; q++)
                d[i][q] = *reinterpret_cast<const float4*>(base + (i * WI + q) * CI);

        float4 t[4][4];
#pragma unroll
        for (int q = 0; q < 4; q++) {
            t[0][q] = f4sub(d[0][q], d[2][q]);
            t[1][q] = f4add(d[1][q], d[2][q]);
            t[2][q] = f4sub(d[2][q], d[1][q]);
            t[3][q] = f4sub(d[1][q], d[3][q]);
        }
        __half* dst0 = g_inT + (long)mp * CI + c0;
#pragma unroll
        for (int i = 0; i < 4; i++) {
            float4 a0 = f4sub(t[i][0], t[i][2]);
            float4 a1 = f4add(t[i][1], t[i][2]);
            float4 a2 = f4sub(t[i][2], t[i][1]);
            float4 a3 = f4sub(t[i][1], t[i][3]);
            const long ps = (long)MPAD * CI;
            *reinterpret_cast<uint2*>(dst0 + (long)(4 * i + 0) * ps) = pack4h(a0);
            *reinterpret_cast<uint2*>(dst0 + (long)(4 * i + 1) * ps) = pack4h(a1);
            *reinterpret_cast<uint2*>(dst0 + (long)(4 * i + 2) * ps) = pack4h(a2);
            *reinterpret_cast<uint2*>(dst0 + (long)(4 * i + 3) * ps) = pack4h(a3);
        }
    } else {
        // ---- weight transform: W~ = G g G^T per (f, c) ----
        const int wt = (b - K1_IN_BLOCKS) * 256 + threadIdx.x;   // < 32768
        const int f = wt >> 7;
        const int c = wt & 127;
        float g[3][3];
#pragma unroll
        for (int i = 0; i < 3; i++)
#pragma unroll
            for (int j = 0; j < 3; j++)
                g[i][j] = w[(long)f * 1152 + (i * 3 + j) * CI + c];
        float u[4][3];
#pragma unroll
        for (int k = 0; k < 3; k++) {
            u[0][k] = g[0][k];
            u[1][k] = 0.5f * (g[0][k] + g[1][k] + g[2][k]);
            u[2][k] = 0.5f * (g[0][k] - g[1][k] + g[2][k]);
            u[3][k] = g[2][k];
        }
        __half* dst = g_wT + (long)f * CI + c;
#pragma unroll
        for (int i = 0; i < 4; i++) {
            float v0 = u[i][0];
            float v1 = 0.5f * (u[i][0] + u[i][1] + u[i][2]);
            float v2 = 0.5f * (u[i][0] - u[i][1] + u[i][2]);
            float v3 = u[i][2];
            const long ps = (long)FO * CI;
            dst[(long)(4 * i + 0) * ps] = __float2half(v0);
            dst[(long)(4 * i + 1) * ps] = __float2half(v1);
            dst[(long)(4 * i + 2) * ps] = __float2half(v2);
            dst[(long)(4 * i + 3) * ps] = __float2half(v3);
        }
    }
}

// ---------------- K2: batched GEMM over pos (2 pos per CTA) ----------------
// Tile 128m' x 128f, 8 warps (2Mx4N), warp tile 64x32 (R5-validated).
// K = 128 per pos -> 2 chunks of 64; 2 pos -> 4 flat chunks, 3-stage pipeline.
#define GSTAGE 32768               // A 16KB + B 16KB
#define GSMEM (3 * GSTAGE)         // 96KB -> 2 CTAs/SM

__device__ __forceinline__ void wg_prefetch(uint32_t sb, int stage, int fc, int pos0,
                                            int m_base, int n_base, int tid) {
    const int pos   = pos0 + (fc >> 1);
    const int khalf = (fc & 1) * 64;
    const uint32_t st = sb + stage * GSTAGE;
    const int row = tid >> 1;
    const int h   = tid & 1;
    const __half* asrc = g_inT + ((long)pos * MPAD + m_base + row) * CI + khalf;
    const __half* bsrc = g_wT  + ((long)pos * FO   + n_base + row) * CI + khalf;
#pragma unroll
    for (int j = 0; j < 4; j++) {
        const int c  = h * 4 + j;
        const int cs = c ^ (row & 7);
        cpa16(st +         row * 128 + cs * 16, asrc + c * 8);
        cpa16(st + 16384 + row * 128 + cs * 16, bsrc + c * 8);
    }
}

__global__ __launch_bounds__(256, 2)
void winograd_gemm() {
    extern __shared__ char smem[];
    const uint32_t sb = smem_u32(smem);
    const int tid  = threadIdx.x;
    const int lane = tid & 31;
    const int wid  = tid >> 5;
    const int warpM = wid >> 2;          // 0..1 -> 64-row slab
    const int warpN = wid & 3;           // 0..3 -> 32-col slab
    const int m_base = blockIdx.x * 128; // 241 tiles over MPAD
    const int n_base = blockIdx.y * 128; // 2 tiles
    const int pos0   = blockIdx.z * 2;   // 8 pos-pairs

    float acc[4][4][4];
#pragma unroll
    for (int i = 0; i < 4; i++)
#pragma unroll
        for (int j = 0; j < 4; j++)
#pragma unroll
            for (int k = 0; k < 4; k++) acc[i][j][k] = 0.0f;

    wg_prefetch(sb, 0, 0, pos0, m_base, n_base, tid); CP_COMMIT();
    wg_prefetch(sb, 1, 1, pos0, m_base, n_base, tid); CP_COMMIT();

#pragma unroll
    for (int fc = 0; fc < 4; fc++) {
        CP_WAIT1();
        __syncthreads();
        if (fc < 2) wg_prefetch(sb, (fc + 2) % 3, fc + 2, pos0, m_base, n_base, tid);
        CP_COMMIT();

        const uint32_t st = sb + (fc % 3) * GSTAGE;
#pragma unroll
        for (int s = 0; s < 4; s++) {
            uint32_t ah[4][4], bh[2][4];
#pragma unroll
            for (int mb = 0; mb < 4; mb++) {
                const int row = warpM * 64 + mb * 16 + (lane & 15);
                const int c   = s * 2 + (lane >> 4);
                const int cs  = c ^ (row & 7);
                ldm4(ah[mb], st + row * 128 + cs * 16);
            }
#pragma unroll
            for (int i = 0; i < 2; i++) {
                const int row = warpN * 32 + i * 16 + (lane & 15);
                const int c   = s * 2 + (lane >> 4);
                const int cs  = c ^ (row & 7);
                ldm4(bh[i], st + 16384 + row * 128 + cs * 16);
            }
#pragma unroll
            for (int mb = 0; mb < 4; mb++)
#pragma unroll
                for (int i = 0; i < 2; i++)
#pragma unroll
                    for (int h = 0; h < 2; h++)
                        mma16816(acc[mb][i * 2 + h], ah[mb],
                                 bh[i][h], bh[i][h + 2]);
        }

        if (fc & 1) {
            // epilogue: write M tile (fp16) for pos = pos0 + (fc>>1)
            const int pos = pos0 + (fc >> 1);
            __half* mbase = g_M + (long)pos * MPAD * FO;
#pragma unroll
            for (int nb = 0; nb < 4; nb++) {
                const int n = n_base + warpN * 32 + nb * 8 + (lane & 3) * 2;
#pragma unroll
                for (int mb = 0; mb < 4; mb++) {
                    const long m0 = (long)m_base + warpM * 64 + mb * 16 + (lane >> 2);
                    const float* c = acc[mb][nb];
                    __half2 h0 = __floats2half2_rn(c[0], c[1]);
                    __half2 h1 = __floats2half2_rn(c[2], c[3]);
                    *reinterpret_cast<__half2*>(mbase + m0 * FO + n)       = h0;
                    *reinterpret_cast<__half2*>(mbase + (m0 + 8) * FO + n) = h1;
                }
            }
            if (fc == 1) {
#pragma unroll
                for (int i = 0; i < 4; i++)
#pragma unroll
                    for (int j = 0; j < 4; j++)
#pragma unroll
                        for (int k = 0; k < 4; k++) acc[i][j][k] = 0.0f;
            }
        }
    }
    CP_WAIT0();
}

// ---------------- K3: output transform y = A^T M A + bias ----------------
__global__ __launch_bounds__(256)
void winograd_output(const float* __restrict__ bias, float* __restrict__ out) {
    const int gt = blockIdx.x * 256 + threadIdx.x;
    const int mp = gt >> 6;              // m' (30752 total: 7688 blocks)
    const int f0 = (gt & 63) * 4;

    float mv[16][4];
#pragma unroll
    for (int p = 0; p < 16; p++) {
        uint2 v = *reinterpret_cast<const uint2*>(
            g_M + ((long)p * MPAD + mp) * FO + f0);
        __half2 lo = *reinterpret_cast<__half2*>(&v.x);
        __half2 hi = *reinterpret_cast<__half2*>(&v.y);
        float2 a = __half22float2(lo);
        float2 bq = __half22float2(hi);
        mv[p][0] = a.x; mv[p][1] = a.y; mv[p][2] = bq.x; mv[p][3] = bq.y;
    }
    const float4 bv = *reinterpret_cast<const float4*>(bias + f0);
    const float bvv[4] = {bv.x, bv.y, bv.z, bv.w};

    float y[2][2][4];
#pragma unroll
    for (int t = 0; t < 4; t++) {
        float z0[4], z1[4];
#pragma unroll
        for (int j = 0; j < 4; j++) {
            z0[j] = mv[j][t] + mv[4 + j][t] + mv[8 + j][t];
            z1[j] = mv[4 + j][t] - mv[8 + j][t] - mv[12 + j][t];
        }
        y[0][0][t] = z0[0] + z0[1] + z0[2] + bvv[t];
        y[0][1][t] = z0[1] - z0[2] - z0[3] + bvv[t];
        y[1][0][t] = z1[0] + z1[1] + z1[2] + bvv[t];
        y[1][1][t] = z1[1] - z1[2] - z1[3] + bvv[t];
    }

    const int n  = mp / (NT * NT);
    const int r  = mp - n * (NT * NT);
    const int th = r / NT;
    const int tw = r - th * NT;
#pragma unroll
    for (int a = 0; a < 2; a++)
#pragma unroll
        for (int bq = 0; bq < 2; bq++) {
            float* dst = out + (((long)(n * HOUT + 2 * th + a)) * HOUT
                                + (2 * tw + bq)) * FO + f0;
            float4 v;
            v.x = y[a][bq][0]; v.y = y[a][bq][1];
            v.z = y[a][bq][2]; v.w = y[a][bq][3];
            *reinterpret_cast<float4*>(dst) = v;
        }
}

extern "C" void kernel_launch(void* const* d_in, const int* in_sizes, int n_in,
                              void* d_out, int out_size) {
    const float* in   = (const float*)d_in[0];
    const float* w    = (const float*)d_in[1];
    const float* bias = (const float*)d_in[2];
    float* out        = (float*)d_out;

    winograd_transform<<<K1_IN_BLOCKS + K1_W_BLOCKS, 256>>>(in, w);

    cudaFuncSetAttribute(winograd_gemm,
                         cudaFuncAttributeMaxDynamicSharedMemorySize, GSMEM);
    dim3 grid(MPAD / 128, 2, 8);   // (241, 2, 8)
    winograd_gemm<<<grid, 256, GSMEM>>>();

    winograd_output<<<7688, 256>>>(bias, out);
}

// round 12
// speedup vs baseline: 1.5730x; 1.1046x over previous
#include <cuda_runtime.h>
#include <cuda_fp16.h>
#include <cstdint>

// Conv (32,64,64,128) NHWC fp32 * w(256,1152) + b -> (32,62,62,256) fp32
// via Winograd F(2x2,3x3) with the output transform FUSED into the GEMM:
//   y(a,b) = bias + sum_p AT[a][p>>2]*AT[b][p&3] * (A~_p . W~_p^T)
// Each CTA owns a full (128 m' x 32 f) tile across all 16 pos, accumulating
// y in registers; no g_M intermediate, no K3 kernel.
// MACs: 16 * 30848 * 256 * 128 = 16.2G

#define NIMG 32
#define HI 64
#define WI 64
#define CI 128
#define FO 256
#define HOUT 62
#define NT 31
#define MW 30752       // 32*31*31
#define MPAD 30848     // 241*128
#define NPOS 16

__device__ __align__(16) __half g_wT[(size_t)NPOS * FO * CI];     // [pos][f][c]
__device__ __align__(16) __half g_inT[(size_t)NPOS * MPAD * CI];  // [pos][m'][c]

// ---------------- common helpers ----------------
__device__ __forceinline__ uint32_t smem_u32(const void* p) {
    uint32_t a;
    asm("{ .reg .u64 t; cvta.to.shared.u64 t, %1; cvt.u32.u64 %0, t; }"
        : "=r"(a) : "l"(p));
    return a;
}
__device__ __forceinline__ void cpa16(uint32_t dst, const void* src) {
    asm volatile("cp.async.cg.shared.global [%0], [%1], 16;"
                 :: "r"(dst), "l"(src));
}
#define CP_COMMIT() asm volatile("cp.async.commit_group;" ::: "memory")
#define CP_WAIT1()  asm volatile("cp.async.wait_group 1;" ::: "memory")
#define CP_WAIT0()  asm volatile("cp.async.wait_group 0;" ::: "memory")

__device__ __forceinline__ void ldm4(uint32_t* r, uint32_t a) {
    asm volatile("ldmatrix.sync.aligned.m8n8.x4.shared.b16 {%0,%1,%2,%3}, [%4];"
                 : "=r"(r[0]), "=r"(r[1]), "=r"(r[2]), "=r"(r[3]) : "r"(a));
}
__device__ __forceinline__ void mma16816(float* c, const uint32_t* a,
                                         uint32_t b0, uint32_t b1) {
    asm volatile(
        "mma.sync.aligned.m16n8k16.row.col.f32.f16.f16.f32 "
        "{%0,%1,%2,%3}, {%4,%5,%6,%7}, {%8,%9}, {%0,%1,%2,%3};"
        : "+f"(c[0]), "+f"(c[1]), "+f"(c[2]), "+f"(c[3])
        : "r"(a[0]), "r"(a[1]), "r"(a[2]), "r"(a[3]), "r"(b0), "r"(b1));
}

__device__ __forceinline__ float4 f4add(float4 a, float4 b) {
    return make_float4(a.x + b.x, a.y + b.y, a.z + b.z, a.w + b.w);
}
__device__ __forceinline__ float4 f4sub(float4 a, float4 b) {
    return make_float4(a.x - b.x, a.y - b.y, a.z - b.z, a.w - b.w);
}
__device__ __forceinline__ uint2 pack4h(float4 v) {
    __half2 p0 = __floats2half2_rn(v.x, v.y);
    __half2 p1 = __floats2half2_rn(v.z, v.w);
    uint2 r;
    r.x = *reinterpret_cast<uint32_t*>(&p0);
    r.y = *reinterpret_cast<uint32_t*>(&p1);
    return r;
}

// ---------------- K1: input + weight transforms (R9-validated) ----------------
#define K1_IN_BLOCKS 3844
#define K1_W_BLOCKS  128

__global__ __launch_bounds__(256)
void winograd_transform(const float* __restrict__ in, const float* __restrict__ w) {
    const int b = blockIdx.x;
    if (b < K1_IN_BLOCKS) {
        const int gt = b * 256 + threadIdx.x;
        const int mp = gt >> 5;
        const int c0 = (gt & 31) * 4;
        const int n  = mp / (NT * NT);
        const int r  = mp - n * (NT * NT);
        const int th = r / NT;
        const int tw = r - th * NT;
        const float* base = in + (((long)(n * HI + 2 * th)) * WI + 2 * tw) * CI + c0;

        float4 t[4][4];
#pragma unroll
        for (int q = 0; q < 4; q++) {
            float4 d0 = *reinterpret_cast<const float4*>(base + (0 * WI + q) * CI);
            float4 d1 = *reinterpret_cast<const float4*>(base + (1 * WI + q) * CI);
            float4 d2 = *reinterpret_cast<const float4*>(base + (2 * WI + q) * CI);
            float4 d3 = *reinterpret_cast<const float4*>(base + (3 * WI + q) * CI);
            t[0][q] = f4sub(d0, d2);
            t[1][q] = f4add(d1, d2);
            t[2][q] = f4sub(d2, d1);
            t[3][q] = f4sub(d1, d3);
        }
        __half* dst0 = g_inT + (long)mp * CI + c0;
#pragma unroll
        for (int i = 0; i < 4; i++) {
            float4 a0 = f4sub(t[i][0], t[i][2]);
            float4 a1 = f4add(t[i][1], t[i][2]);
            float4 a2 = f4sub(t[i][2], t[i][1]);
            float4 a3 = f4sub(t[i][1], t[i][3]);
            const long ps = (long)MPAD * CI;
            *reinterpret_cast<uint2*>(dst0 + (long)(4 * i + 0) * ps) = pack4h(a0);
            *reinterpret_cast<uint2*>(dst0 + (long)(4 * i + 1) * ps) = pack4h(a1);
            *reinterpret_cast<uint2*>(dst0 + (long)(4 * i + 2) * ps) = pack4h(a2);
            *reinterpret_cast<uint2*>(dst0 + (long)(4 * i + 3) * ps) = pack4h(a3);
        }
    } else {
        const int wt = (b - K1_IN_BLOCKS) * 256 + threadIdx.x;
        const int f = wt >> 7;
        const int c = wt & 127;
        float g[3][3];
#pragma unroll
        for (int i = 0; i < 3; i++)
#pragma unroll
            for (int j = 0; j < 3; j++)
                g[i][j] = w[(long)f * 1152 + (i * 3 + j) * CI + c];
        float u[4][3];
#pragma unroll
        for (int k = 0; k < 3; k++) {
            u[0][k] = g[0][k];
            u[1][k] = 0.5f * (g[0][k] + g[1][k] + g[2][k]);
            u[2][k] = 0.5f * (g[0][k] - g[1][k] + g[2][k]);
            u[3][k] = g[2][k];
        }
        __half* dst = g_wT + (long)f * CI + c;
#pragma unroll
        for (int i = 0; i < 4; i++) {
            float v0 = u[i][0];
            float v1 = 0.5f * (u[i][0] + u[i][1] + u[i][2]);
            float v2 = 0.5f * (u[i][0] - u[i][1] + u[i][2]);
            float v3 = u[i][2];
            const long ps = (long)FO * CI;
            dst[(long)(4 * i + 0) * ps] = __float2half(v0);
            dst[(long)(4 * i + 1) * ps] = __float2half(v1);
            dst[(long)(4 * i + 2) * ps] = __float2half(v2);
            dst[(long)(4 * i + 3) * ps] = __float2half(v3);
        }
    }
}

// ---------------- K2: fused GEMM + output transform ----------------
// CTA tile: 128 m' x 32 f; 8 warps, each warp 16 m-rows x 32 f.
// Loops pos 0..15; per pos K=128 as 2 chunks of 64; 3-stage cp.async pipeline.
#define FSTAGE 20480               // A 16KB + B 4KB
#define FSMEM (3 * FSTAGE)         // 61440 -> 2 CTAs/SM
#define OFF_B 16384

__device__ __forceinline__ void f_prefetch(uint32_t sb, int stage, int fc,
                                           int m_base, int f_base, int tid) {
    const int pos   = fc >> 1;
    const int khalf = (fc & 1) * 64;
    const uint32_t st = sb + stage * FSTAGE;
    // A: 128 rows x 64 halves; 2 threads/row, 4 x 16B each
    {
        const int row = tid >> 1;
        const int h   = tid & 1;
        const __half* asrc = g_inT + ((long)pos * MPAD + m_base + row) * CI + khalf;
#pragma unroll
        for (int j = 0; j < 4; j++) {
            const int c  = h * 4 + j;
            const int cs = c ^ (row & 7);
            cpa16(st + row * 128 + cs * 16, asrc + c * 8);
        }
    }
    // B: 32 rows x 64 halves; 8 threads/row, 1 x 16B each
    {
        const int row = tid >> 3;
        const int c   = tid & 7;
        const int cs  = c ^ (row & 7);
        const __half* bsrc = g_wT + ((long)pos * FO + f_base + row) * CI + khalf;
        cpa16(st + OFF_B + row * 128 + cs * 16, bsrc + c * 8);
    }
}

__global__ __launch_bounds__(256, 2)
void winograd_fused(const float* __restrict__ bias, float* __restrict__ out) {
    extern __shared__ char smem[];
    const uint32_t sb = smem_u32(smem);
    const int tid  = threadIdx.x;
    const int lane = tid & 31;
    const int wid  = tid >> 5;           // 0..7 -> 16-row slab
    const int m_base = blockIdx.x * 128; // 241 tiles
    const int f_base = blockIdx.y * 32;  // 8 tiles

    // y accumulators: [a][b][nb][4], init to bias
    float y[2][2][4][4];
#pragma unroll
    for (int nb = 0; nb < 4; nb++) {
        const int f = f_base + nb * 8 + (lane & 3) * 2;
        const float2 bv = *reinterpret_cast<const float2*>(bias + f);
#pragma unroll
        for (int a = 0; a < 2; a++)
#pragma unroll
            for (int b = 0; b < 2; b++) {
                y[a][b][nb][0] = bv.x; y[a][b][nb][1] = bv.y;
                y[a][b][nb][2] = bv.x; y[a][b][nb][3] = bv.y;
            }
    }

    f_prefetch(sb, 0, 0, m_base, f_base, tid); CP_COMMIT();
    f_prefetch(sb, 1, 1, m_base, f_base, tid); CP_COMMIT();

    const float AT0[4] = {1.f, 1.f, 1.f, 0.f};
    const float AT1[4] = {0.f, 1.f, -1.f, -1.f};

#pragma unroll
    for (int pos = 0; pos < NPOS; pos++) {
        float acc[4][4];
#pragma unroll
        for (int nb = 0; nb < 4; nb++)
#pragma unroll
            for (int k = 0; k < 4; k++) acc[nb][k] = 0.0f;

#pragma unroll
        for (int half = 0; half < 2; half++) {
            const int fc = pos * 2 + half;
            CP_WAIT1();
            __syncthreads();
            if (fc < 2 * NPOS - 2)
                f_prefetch(sb, (fc + 2) % 3, fc + 2, m_base, f_base, tid);
            CP_COMMIT();

            const uint32_t st = sb + (fc % 3) * FSTAGE;
#pragma unroll
            for (int s = 0; s < 4; s++) {
                uint32_t ah[4], bh[2][4];
                const int c  = s * 2 + (lane >> 4);
                const int rl = lane & 15;
                {
                    const int row = wid * 16 + rl;
                    const int cs  = c ^ (row & 7);
                    ldm4(ah, st + row * 128 + cs * 16);
                }
#pragma unroll
                for (int i = 0; i < 2; i++) {
                    const int row = i * 16 + rl;
                    const int cs  = c ^ (row & 7);
                    ldm4(bh[i], st + OFF_B + row * 128 + cs * 16);
                }
#pragma unroll
                for (int i = 0; i < 2; i++)
#pragma unroll
                    for (int h = 0; h < 2; h++)
                        mma16816(acc[i * 2 + h], ah, bh[i][h], bh[i][h + 2]);
            }
        }

        // fold this pos into y with compile-time +-1 coefficients
        const int pi = pos >> 2, pj = pos & 3;
#pragma unroll
        for (int a = 0; a < 2; a++) {
            const float ca = (a == 0) ? AT0[pi] : AT1[pi];
            if (ca == 0.f) continue;
#pragma unroll
            for (int b = 0; b < 2; b++) {
                const float cb = (b == 0) ? AT0[pj] : AT1[pj];
                if (cb == 0.f) continue;
                const float cc = ca * cb;
#pragma unroll
                for (int nb = 0; nb < 4; nb++)
#pragma unroll
                    for (int k = 0; k < 4; k++)
                        y[a][b][nb][k] += cc * acc[nb][k];
            }
        }
    }
    CP_WAIT0();

    // ---- store: decode m' -> (n, th, tw), write 2x2 outputs ----
#pragma unroll
    for (int rr = 0; rr < 2; rr++) {
        const int mp = m_base + wid * 16 + (lane >> 2) + rr * 8;
        if (mp >= MW) continue;
        const int n  = mp / (NT * NT);
        const int r  = mp - n * (NT * NT);
        const int th = r / NT;
        const int tw = r - th * NT;
#pragma unroll
        for (int a = 0; a < 2; a++)
#pragma unroll
            for (int b = 0; b < 2; b++) {
                float* dst = out + (((long)(n * HOUT + 2 * th + a)) * HOUT
                                    + (2 * tw + b)) * FO;
#pragma unroll
                for (int nb = 0; nb < 4; nb++) {
                    const int f = f_base + nb * 8 + (lane & 3) * 2;
                    float2 v;
                    v.x = y[a][b][nb][rr * 2 + 0];
                    v.y = y[a][b][nb][rr * 2 + 1];
                    *reinterpret_cast<float2*>(dst + f) = v;
                }
            }
    }
}

extern "C" void kernel_launch(void* const* d_in, const int* in_sizes, int n_in,
                              void* d_out, int out_size) {
    const float* in   = (const float*)d_in[0];
    const float* w    = (const float*)d_in[1];
    const float* bias = (const float*)d_in[2];
    float* out        = (float*)d_out;

    winograd_transform<<<K1_IN_BLOCKS + K1_W_BLOCKS, 256>>>(in, w);

    cudaFuncSetAttribute(winograd_fused,
                         cudaFuncAttributeMaxDynamicSharedMemorySize, FSMEM);
    dim3 grid(MPAD / 128, 8);   // (241, 8)
    winograd_fused<<<grid, 256, FSMEM>>>(bias, out);
}

// round 13
// speedup vs baseline: 1.5892x; 1.0103x over previous
#include <cuda_runtime.h>
#include <cuda_fp16.h>
#include <cstdint>

// Conv (32,64,64,128) NHWC fp32 * w(256,1152) + b -> (32,62,62,256) fp32
// via Winograd F(2x2,3x3) with the output transform FUSED into the GEMM:
//   y(a,b) = bias + sum_p AT[a][p>>2]*AT[b][p&3] * (A~_p . W~_p^T)
// R13 = R12 + grid order swap: blockIdx.x = f-tile (8), blockIdx.y = m-tile
// (241), so the 8 CTAs sharing an A-slice are co-resident -> A re-reads hit L2.
// MACs: 16 * 30848 * 256 * 128 = 16.2G

#define NIMG 32
#define HI 64
#define WI 64
#define CI 128
#define FO 256
#define HOUT 62
#define NT 31
#define MW 30752       // 32*31*31
#define MPAD 30848     // 241*128
#define NPOS 16

__device__ __align__(16) __half g_wT[(size_t)NPOS * FO * CI];     // [pos][f][c]
__device__ __align__(16) __half g_inT[(size_t)NPOS * MPAD * CI];  // [pos][m'][c]

// ---------------- common helpers ----------------
__device__ __forceinline__ uint32_t smem_u32(const void* p) {
    uint32_t a;
    asm("{ .reg .u64 t; cvta.to.shared.u64 t, %1; cvt.u32.u64 %0, t; }"
        : "=r"(a) : "l"(p));
    return a;
}
__device__ __forceinline__ void cpa16(uint32_t dst, const void* src) {
    asm volatile("cp.async.cg.shared.global [%0], [%1], 16;"
                 :: "r"(dst), "l"(src));
}
#define CP_COMMIT() asm volatile("cp.async.commit_group;" ::: "memory")
#define CP_WAIT1()  asm volatile("cp.async.wait_group 1;" ::: "memory")
#define CP_WAIT0()  asm volatile("cp.async.wait_group 0;" ::: "memory")

__device__ __forceinline__ void ldm4(uint32_t* r, uint32_t a) {
    asm volatile("ldmatrix.sync.aligned.m8n8.x4.shared.b16 {%0,%1,%2,%3}, [%4];"
                 : "=r"(r[0]), "=r"(r[1]), "=r"(r[2]), "=r"(r[3]) : "r"(a));
}
__device__ __forceinline__ void mma16816(float* c, const uint32_t* a,
                                         uint32_t b0, uint32_t b1) {
    asm volatile(
        "mma.sync.aligned.m16n8k16.row.col.f32.f16.f16.f32 "
        "{%0,%1,%2,%3}, {%4,%5,%6,%7}, {%8,%9}, {%0,%1,%2,%3};"
        : "+f"(c[0]), "+f"(c[1]), "+f"(c[2]), "+f"(c[3])
        : "r"(a[0]), "r"(a[1]), "r"(a[2]), "r"(a[3]), "r"(b0), "r"(b1));
}

__device__ __forceinline__ float4 f4add(float4 a, float4 b) {
    return make_float4(a.x + b.x, a.y + b.y, a.z + b.z, a.w + b.w);
}
__device__ __forceinline__ float4 f4sub(float4 a, float4 b) {
    return make_float4(a.x - b.x, a.y - b.y, a.z - b.z, a.w - b.w);
}
__device__ __forceinline__ uint2 pack4h(float4 v) {
    __half2 p0 = __floats2half2_rn(v.x, v.y);
    __half2 p1 = __floats2half2_rn(v.z, v.w);
    uint2 r;
    r.x = *reinterpret_cast<uint32_t*>(&p0);
    r.y = *reinterpret_cast<uint32_t*>(&p1);
    return r;
}

// ---------------- K1: input + weight transforms (R9-validated) ----------------
#define K1_IN_BLOCKS 3844
#define K1_W_BLOCKS  128

__global__ __launch_bounds__(256)
void winograd_transform(const float* __restrict__ in, const float* __restrict__ w) {
    const int b = blockIdx.x;
    if (b < K1_IN_BLOCKS) {
        const int gt = b * 256 + threadIdx.x;
        const int mp = gt >> 5;
        const int c0 = (gt & 31) * 4;
        const int n  = mp / (NT * NT);
        const int r  = mp - n * (NT * NT);
        const int th = r / NT;
        const int tw = r - th * NT;
        const float* base = in + (((long)(n * HI + 2 * th)) * WI + 2 * tw) * CI + c0;

        float4 t[4][4];
#pragma unroll
        for (int q = 0; q < 4; q++) {
            float4 d0 = *reinterpret_cast<const float4*>(base + (0 * WI + q) * CI);
            float4 d1 = *reinterpret_cast<const float4*>(base + (1 * WI + q) * CI);
            float4 d2 = *reinterpret_cast<const float4*>(base + (2 * WI + q) * CI);
            float4 d3 = *reinterpret_cast<const float4*>(base + (3 * WI + q) * CI);
            t[0][q] = f4sub(d0, d2);
            t[1][q] = f4add(d1, d2);
            t[2][q] = f4sub(d2, d1);
            t[3][q] = f4sub(d1, d3);
        }
        __half* dst0 = g_inT + (long)mp * CI + c0;
#pragma unroll
        for (int i = 0; i < 4; i++) {
            float4 a0 = f4sub(t[i][0], t[i][2]);
            float4 a1 = f4add(t[i][1], t[i][2]);
            float4 a2 = f4sub(t[i][2], t[i][1]);
            float4 a3 = f4sub(t[i][1], t[i][3]);
            const long ps = (long)MPAD * CI;
            *reinterpret_cast<uint2*>(dst0 + (long)(4 * i + 0) * ps) = pack4h(a0);
            *reinterpret_cast<uint2*>(dst0 + (long)(4 * i + 1) * ps) = pack4h(a1);
            *reinterpret_cast<uint2*>(dst0 + (long)(4 * i + 2) * ps) = pack4h(a2);
            *reinterpret_cast<uint2*>(dst0 + (long)(4 * i + 3) * ps) = pack4h(a3);
        }
    } else {
        const int wt = (b - K1_IN_BLOCKS) * 256 + threadIdx.x;
        const int f = wt >> 7;
        const int c = wt & 127;
        float g[3][3];
#pragma unroll
        for (int i = 0; i < 3; i++)
#pragma unroll
            for (int j = 0; j < 3; j++)
                g[i][j] = w[(long)f * 1152 + (i * 3 + j) * CI + c];
        float u[4][3];
#pragma unroll
        for (int k = 0; k < 3; k++) {
            u[0][k] = g[0][k];
            u[1][k] = 0.5f * (g[0][k] + g[1][k] + g[2][k]);
            u[2][k] = 0.5f * (g[0][k] - g[1][k] + g[2][k]);
            u[3][k] = g[2][k];
        }
        __half* dst = g_wT + (long)f * CI + c;
#pragma unroll
        for (int i = 0; i < 4; i++) {
            float v0 = u[i][0];
            float v1 = 0.5f * (u[i][0] + u[i][1] + u[i][2]);
            float v2 = 0.5f * (u[i][0] - u[i][1] + u[i][2]);
            float v3 = u[i][2];
            const long ps = (long)FO * CI;
            dst[(long)(4 * i + 0) * ps] = __float2half(v0);
            dst[(long)(4 * i + 1) * ps] = __float2half(v1);
            dst[(long)(4 * i + 2) * ps] = __float2half(v2);
            dst[(long)(4 * i + 3) * ps] = __float2half(v3);
        }
    }
}

// ---------------- K2: fused GEMM + output transform ----------------
// CTA tile: 128 m' x 32 f; 8 warps, each warp 16 m-rows x 32 f.
// Loops pos 0..15; per pos K=128 as 2 chunks of 64; 3-stage cp.async pipeline.
#define FSTAGE 20480               // A 16KB + B 4KB
#define FSMEM (3 * FSTAGE)         // 61440 -> 2 CTAs/SM
#define OFF_B 16384

__device__ __forceinline__ void f_prefetch(uint32_t sb, int stage, int fc,
                                           int m_base, int f_base, int tid) {
    const int pos   = fc >> 1;
    const int khalf = (fc & 1) * 64;
    const uint32_t st = sb + stage * FSTAGE;
    // A: 128 rows x 64 halves; 2 threads/row, 4 x 16B each
    {
        const int row = tid >> 1;
        const int h   = tid & 1;
        const __half* asrc = g_inT + ((long)pos * MPAD + m_base + row) * CI + khalf;
#pragma unroll
        for (int j = 0; j < 4; j++) {
            const int c  = h * 4 + j;
            const int cs = c ^ (row & 7);
            cpa16(st + row * 128 + cs * 16, asrc + c * 8);
        }
    }
    // B: 32 rows x 64 halves; 8 threads/row, 1 x 16B each
    {
        const int row = tid >> 3;
        const int c   = tid & 7;
        const int cs  = c ^ (row & 7);
        const __half* bsrc = g_wT + ((long)pos * FO + f_base + row) * CI + khalf;
        cpa16(st + OFF_B + row * 128 + cs * 16, bsrc + c * 8);
    }
}

__global__ __launch_bounds__(256, 2)
void winograd_fused(const float* __restrict__ bias, float* __restrict__ out) {
    extern __shared__ char smem[];
    const uint32_t sb = smem_u32(smem);
    const int tid  = threadIdx.x;
    const int lane = tid & 31;
    const int wid  = tid >> 5;           // 0..7 -> 16-row slab
    const int f_base = blockIdx.x * 32;  // 8 tiles  (fast dim -> co-resident)
    const int m_base = blockIdx.y * 128; // 241 tiles

    // y accumulators: [a][b][nb][4], init to bias
    float y[2][2][4][4];
#pragma unroll
    for (int nb = 0; nb < 4; nb++) {
        const int f = f_base + nb * 8 + (lane & 3) * 2;
        const float2 bv = *reinterpret_cast<const float2*>(bias + f);
#pragma unroll
        for (int a = 0; a < 2; a++)
#pragma unroll
            for (int b = 0; b < 2; b++) {
                y[a][b][nb][0] = bv.x; y[a][b][nb][1] = bv.y;
                y[a][b][nb][2] = bv.x; y[a][b][nb][3] = bv.y;
            }
    }

    f_prefetch(sb, 0, 0, m_base, f_base, tid); CP_COMMIT();
    f_prefetch(sb, 1, 1, m_base, f_base, tid); CP_COMMIT();

    const float AT0[4] = {1.f, 1.f, 1.f, 0.f};
    const float AT1[4] = {0.f, 1.f, -1.f, -1.f};

#pragma unroll
    for (int pos = 0; pos < NPOS; pos++) {
        float acc[4][4];
#pragma unroll
        for (int nb = 0; nb < 4; nb++)
#pragma unroll
            for (int k = 0; k < 4; k++) acc[nb][k] = 0.0f;

#pragma unroll
        for (int half = 0; half < 2; half++) {
            const int fc = pos * 2 + half;
            CP_WAIT1();
            __syncthreads();
            if (fc < 2 * NPOS - 2)
                f_prefetch(sb, (fc + 2) % 3, fc + 2, m_base, f_base, tid);
            CP_COMMIT();

            const uint32_t st = sb + (fc % 3) * FSTAGE;
#pragma unroll
            for (int s = 0; s < 4; s++) {
                uint32_t ah[4], bh[2][4];
                const int c  = s * 2 + (lane >> 4);
                const int rl = lane & 15;
                {
                    const int row = wid * 16 + rl;
                    const int cs  = c ^ (row & 7);
                    ldm4(ah, st + row * 128 + cs * 16);
                }
#pragma unroll
                for (int i = 0; i < 2; i++) {
                    const int row = i * 16 + rl;
                    const int cs  = c ^ (row & 7);
                    ldm4(bh[i], st + OFF_B + row * 128 + cs * 16);
                }
#pragma unroll
                for (int i = 0; i < 2; i++)
#pragma unroll
                    for (int h = 0; h < 2; h++)
                        mma16816(acc[i * 2 + h], ah, bh[i][h], bh[i][h + 2]);
            }
        }

        // fold this pos into y with compile-time +-1 coefficients
        const int pi = pos >> 2, pj = pos & 3;
#pragma unroll
        for (int a = 0; a < 2; a++) {
            const float ca = (a == 0) ? AT0[pi] : AT1[pi];
            if (ca == 0.f) continue;
#pragma unroll
            for (int b = 0; b < 2; b++) {
                const float cb = (b == 0) ? AT0[pj] : AT1[pj];
                if (cb == 0.f) continue;
                const float cc = ca * cb;
#pragma unroll
                for (int nb = 0; nb < 4; nb++)
#pragma unroll
                    for (int k = 0; k < 4; k++)
                        y[a][b][nb][k] += cc * acc[nb][k];
            }
        }
    }
    CP_WAIT0();

    // ---- store: decode m' -> (n, th, tw), write 2x2 outputs ----
#pragma unroll
    for (int rr = 0; rr < 2; rr++) {
        const int mp = m_base + wid * 16 + (lane >> 2) + rr * 8;
        if (mp >= MW) continue;
        const int n  = mp / (NT * NT);
        const int r  = mp - n * (NT * NT);
        const int th = r / NT;
        const int tw = r - th * NT;
#pragma unroll
        for (int a = 0; a < 2; a++)
#pragma unroll
            for (int b = 0; b < 2; b++) {
                float* dst = out + (((long)(n * HOUT + 2 * th + a)) * HOUT
                                    + (2 * tw + b)) * FO;
#pragma unroll
                for (int nb = 0; nb < 4; nb++) {
                    const int f = f_base + nb * 8 + (lane & 3) * 2;
                    float2 v;
                    v.x = y[a][b][nb][rr * 2 + 0];
                    v.y = y[a][b][nb][rr * 2 + 1];
                    *reinterpret_cast<float2*>(dst + f) = v;
                }
            }
    }
}

extern "C" void kernel_launch(void* const* d_in, const int* in_sizes, int n_in,
                              void* d_out, int out_size) {
    const float* in   = (const float*)d_in[0];
    const float* w    = (const float*)d_in[1];
    const float* bias = (const float*)d_in[2];
    float* out        = (float*)d_out;

    winograd_transform<<<K1_IN_BLOCKS + K1_W_BLOCKS, 256>>>(in, w);

    cudaFuncSetAttribute(winograd_fused,
                         cudaFuncAttributeMaxDynamicSharedMemorySize, FSMEM);
    dim3 grid(8, MPAD / 128);   // (8 f-tiles, 241 m-tiles) — f fastest
    winograd_fused<<<grid, 256, FSMEM>>>(bias, out);
}